// round 8
// baseline (speedup 1.0000x reference)
#include <cuda_runtime.h>
#include <cuda_bf16.h>

// KOrderGPMap: B=32, L=64, C=4. x one-hot => s_l = 4*l + idx[b,l].
// phi[b] = th0 + sum th1[s_l] + sum_{l0<l1} th2[s0*256+s1]
//        + sum_{l0<l1<l2} th3[(s0<<16)+(s1<<8)+s2].
//
// Inverted structure: one block per PAIR (l0,l1). Stream all 16 (c0,c1)
// suffix rows of theta3 into smem (coalesced, each sector read once
// globally), then all 32 batches gather from smem. Batches share loads.

#define B 32
#define L 64
#define NT 128
#define NPAIRS 2016
#define PITCH 260   // floats per smem suffix row (>= 252, mult of 4)

__device__ unsigned char d_c[B * L];      // transposed: d_c[l*32 + b]
__device__ float d_scratch[B * 64];       // batch b at [b*64] (256B stride)

// ---- init: decode one-hot -> c table; order-1 + theta0 into scratch ----
__global__ __launch_bounds__(NT)
void init_kernel(const float* __restrict__ x,
                 const float* __restrict__ th0,
                 const float* __restrict__ th1)
{
    __shared__ unsigned char sc[B * L];   // sc[l*32+b]
    const int tid = threadIdx.x;

    for (int i = tid; i < B * L; i += NT) {
        const int b = i >> 6, l = i & 63;
        const float4 v = reinterpret_cast<const float4*>(x)[i];
        const unsigned char c =
            (unsigned char)(int)(v.y + 2.0f * v.z + 3.0f * v.w + 0.5f);
        sc[l * 32 + b] = c;
        d_c[l * 32 + b] = c;
    }
    __syncthreads();

    // order-1: 4 threads per batch, 16 gathers each, shfl-reduce.
    const int b = tid >> 2, q = tid & 3;
    float sum = (q == 0) ? th0[0] : 0.0f;
    #pragma unroll
    for (int l = q; l < L; l += 4)
        sum += __ldg(&th1[4 * l + sc[l * 32 + b]]);
    sum += __shfl_xor_sync(0xffffffffu, sum, 1);
    sum += __shfl_xor_sync(0xffffffffu, sum, 2);
    if (q == 0) d_scratch[b * 64] = sum;
}

// ---- main: per-pair dense theta3 suffixes + per-batch smem gathers ----
__global__ __launch_bounds__(NT)
void kgp5_kernel(const float* __restrict__ th2,
                 const float* __restrict__ th3)
{
    __shared__ float suf[16 * PITCH];      // [c0*4+c1][4*(l2-l1-1)+c2]
    __shared__ unsigned char cs[B * L];    // cs[l*32+b]
    __shared__ float t2s[16];
    __shared__ float red[NT];

    const int tid  = threadIdx.x;
    const int warp = tid >> 5;
    const int lane = tid & 31;

    // decode pair index -> (l0, l1), l0 < l1
    int p = blockIdx.x, l0 = 0;
    while (p >= 63 - l0) { p -= 63 - l0; ++l0; }
    const int l1 = l0 + 1 + p;
    const int w  = 63 - l1;                // number of l2 values (float4s/row)

    // c table: one int4 per thread (2048 B)
    reinterpret_cast<int4*>(cs)[tid] = reinterpret_cast<const int4*>(d_c)[tid];

    // theta2 combos
    if (tid < 16)
        t2s[tid] = __ldg(&th2[(4 * l0 + (tid >> 2)) * 256 + 4 * l1 + (tid & 3)]);

    // stream 16 suffix rows, coalesced float4 loads
    const float4* __restrict__ t3v = reinterpret_cast<const float4*>(th3);
    for (int r = warp; r < 16; r += 4) {
        const int base4 = ((4 * l0 + (r >> 2)) << 14) + ((4 * l1 + (r & 3)) << 6)
                        + (l1 + 1);
        float4* dst = reinterpret_cast<float4*>(&suf[r * PITCH]);
        for (int j = lane; j < w; j += 32)
            dst[j] = __ldg(&t3v[base4 + j]);
    }
    __syncthreads();

    // compute: warp g, lane b (= batch). Each thread sums l2 = l1+1+g step 4.
    const int b  = lane;
    const int cc = cs[l0 * 32 + b] * 4 + cs[l1 * 32 + b];
    const float* __restrict__ sufb = &suf[cc * PITCH];

    float acc = (warp == 0) ? t2s[cc] : 0.0f;   // order-2, once per batch
    #pragma unroll 4
    for (int l2 = l1 + 1 + warp; l2 < L; l2 += 4)
        acc += sufb[4 * (l2 - l1 - 1) + cs[l2 * 32 + b]];

    red[warp * 32 + b] = acc;
    __syncthreads();

    if (warp == 0) {
        const float tot = red[b] + red[32 + b] + red[64 + b] + red[96 + b];
        atomicAdd(&d_scratch[b * 64], tot);     // 256B-spread: parallel slices
    }
}

// ---- final: scratch -> out ----
__global__ void final_kernel(float* __restrict__ out) {
    if (threadIdx.x < B) out[threadIdx.x] = d_scratch[threadIdx.x * 64];
}

extern "C" void kernel_launch(void* const* d_in, const int* in_sizes, int n_in,
                              void* d_out, int out_size) {
    const float* x   = (const float*)d_in[0];
    const float* th0 = (const float*)d_in[1];
    const float* th1 = (const float*)d_in[2];
    const float* th2 = (const float*)d_in[3];
    const float* th3 = (const float*)d_in[4];
    float* out = (float*)d_out;

    init_kernel<<<1, NT>>>(x, th0, th1);
    kgp5_kernel<<<NPAIRS, NT>>>(th2, th3);
    final_kernel<<<1, 32>>>(out);
}

// round 9
// speedup vs baseline: 1.3213x; 1.3213x over previous
#include <cuda_runtime.h>
#include <cuda_bf16.h>

// KOrderGPMap: B=32, L=64, C=4. x one-hot => s_l = 4*l + idx[b,l].
// phi[b] = th0 + sum th1[s_l] + sum_{l0<l1} th2[s0*256+s1]
//        + sum_{l0<l1<l2} th3[(s0<<16)+(s1<<8)+s2].
//
// One block per PAIR (l0,l1): stream the 16 (c0,c1) theta3 suffix rows into
// smem (coalesced; each theta3 sector read exactly once chip-wide), then all
// 32 batches gather from smem. Order-1 handled by the empty pair (62,63).

#define B 32
#define L 64
#define NT 128
#define NPAIRS 2016
#define PITCH 260   // floats per smem suffix row (>= 252, mult of 4)

__device__ unsigned char d_c[B * L];      // transposed: d_c[l*32 + b]

// ---- prep: zero out + decode one-hot -> c table (no serial chains) ----
__global__ __launch_bounds__(256)
void prep_kernel(const float* __restrict__ x, float* __restrict__ out) {
    const int tid = threadIdx.x;
    if (tid < B) out[tid] = 0.0f;
    #pragma unroll
    for (int k = 0; k < 8; ++k) {
        const int i = tid + k * 256;          // i = b*64 + l
        const float4 v = reinterpret_cast<const float4*>(x)[i];
        const unsigned char c =
            (unsigned char)(int)(v.y + 2.0f * v.z + 3.0f * v.w + 0.5f);
        d_c[(i & 63) * 32 + (i >> 6)] = c;    // [l*32 + b]
    }
}

// ---- main: per-pair dense theta3 suffixes + per-batch smem gathers ----
__global__ __launch_bounds__(NT)
void kgp6_kernel(const float* __restrict__ th0,
                 const float* __restrict__ th1,
                 const float* __restrict__ th2,
                 const float* __restrict__ th3,
                 float* __restrict__ out)
{
    __shared__ float suf[16 * PITCH];      // [c0*4+c1][4*(l2-l1-1)+c2]
    __shared__ unsigned char cs[B * L];    // cs[l*32+b]
    __shared__ float t2s[16];
    __shared__ float red[NT];

    const int tid  = threadIdx.x;
    const int warp = tid >> 5;
    const int lane = tid & 31;

    // decode pair index -> (l0, l1), l0 < l1
    int p = blockIdx.x, l0 = 0;
    while (p >= 63 - l0) { p -= 63 - l0; ++l0; }
    const int l1 = l0 + 1 + p;
    const int w  = 63 - l1;                // number of l2 values (float4s/row)

    // c table: one int4 per thread (2048 B total)
    reinterpret_cast<int4*>(cs)[tid] = reinterpret_cast<const int4*>(d_c)[tid];

    // theta2 combos for this pair
    if (tid < 16)
        t2s[tid] = __ldg(&th2[(4 * l0 + (tid >> 2)) * 256 + 4 * l1 + (tid & 3)]);

    // stream 16 suffix rows, coalesced float4 loads
    const float4* __restrict__ t3v = reinterpret_cast<const float4*>(th3);
    for (int r = warp; r < 16; r += 4) {
        const int base4 = ((4 * l0 + (r >> 2)) << 14) + ((4 * l1 + (r & 3)) << 6)
                        + (l1 + 1);
        float4* dst = reinterpret_cast<float4*>(&suf[r * PITCH]);
        for (int j = lane; j < w; j += 32)
            dst[j] = __ldg(&t3v[base4 + j]);
    }
    __syncthreads();

    // compute: warp g, lane b (= batch). Thread sums l2 = l1+1+g step 4.
    const int b  = lane;
    const int cc = cs[l0 * 32 + b] * 4 + cs[l1 * 32 + b];
    const float* __restrict__ sufb = &suf[cc * PITCH];

    float acc = (warp == 0) ? t2s[cc] : 0.0f;   // order-2, once per batch
    #pragma unroll 4
    for (int l2 = l1 + 1 + warp; l2 < L; l2 += 4)
        acc += sufb[4 * (l2 - l1 - 1) + cs[l2 * 32 + b]];

    // order-1 + theta0: pair (62,63) has w=0 -> spare capacity. Warps 1,2
    // each cover 32 positions for all 32 batches (lane = batch).
    if (blockIdx.x == NPAIRS - 1 && (warp == 1 || warp == 2)) {
        const int lbase = (warp - 1) * 32;
        #pragma unroll
        for (int l = lbase; l < lbase + 32; ++l)
            acc += __ldg(&th1[4 * l + cs[l * 32 + b]]);
        if (warp == 1) acc += th0[0];   // exactly once per batch
    }

    red[warp * 32 + b] = acc;
    __syncthreads();

    if (warp == 0) {
        float tot = red[b] + red[32 + b] + red[64 + b] + red[96 + b];
        atomicAdd(&out[b], tot);
    }
}

extern "C" void kernel_launch(void* const* d_in, const int* in_sizes, int n_in,
                              void* d_out, int out_size) {
    const float* x   = (const float*)d_in[0];
    const float* th0 = (const float*)d_in[1];
    const float* th1 = (const float*)d_in[2];
    const float* th2 = (const float*)d_in[3];
    const float* th3 = (const float*)d_in[4];
    float* out = (float*)d_out;

    prep_kernel<<<1, 256>>>(x, out);
    kgp6_kernel<<<NPAIRS, NT>>>(th0, th1, th2, th3, out);
}